// round 12
// baseline (speedup 1.0000x reference)
#include <cuda_runtime.h>
#include <cuda_bf16.h>
#include <cstdint>
#include <math.h>

#define N_NODES 50000
#define N_EDGES 500000
#define ET (N_EDGES + N_NODES)   // with self loops
#define IN_CH 256
#define F1 512                   // 8 heads * 64
#define HID 64
#define HEADS 8
#define OUT_CH 16
#define KP 768                   // K' = 3*256 for hi/lo-split bf16 GEMM

// ---------------- scratch (device globals; no allocation allowed) ----------------
__device__ __align__(16) float g_h1[(size_t)N_NODES * F1];     // x @ W1
__device__ __align__(16) float g_h2[(size_t)N_NODES * F1];     // layer-1 output (post ELU)
__device__ __align__(16) float g_as1[N_NODES * HEADS];
__device__ __align__(16) float g_ad1[N_NODES * HEADS];
__device__ __align__(16) float g_t2[N_NODES * OUT_CH];         // h2 @ W2
__device__ __align__(16) float g_as2[N_NODES];
__device__ __align__(16) float g_ad2[N_NODES];
__device__ __align__(16) __nv_bfloat16 g_xa[(size_t)N_NODES * KP];  // [xhi | xhi | xlo]
__device__ __align__(16) __nv_bfloat16 g_wb[(size_t)F1 * KP];       // per-out-col rows [Whi | Wlo | Whi]
__device__ int      g_deg[N_NODES + 1];
__device__ int      g_off[N_NODES + 1];
__device__ int      g_cur[N_NODES];
__device__ int      g_esrc[ET];                  // src id per dst-sorted edge
__device__ int      g_is64;
__device__ unsigned g_gmax1[HEADS];              // order-uint global max of as1 per head
__device__ unsigned g_gmax2;                     // order-uint global max of as2
#define NSCB 196                                 // ceil(50000/256)
__device__ int   g_bsum[NSCB];
__device__ int   g_bbase[NSCB];

// ---------------- helpers ----------------
__device__ __forceinline__ uint32_t smem_u32(const void* p) {
    uint32_t a;
    asm("{ .reg .u64 t; cvta.to.shared.u64 t, %1; cvt.u32.u64 %0, t; }" : "=r"(a) : "l"(p));
    return a;
}
template <int N>
__device__ __forceinline__ void cpasync_wait() {
    asm volatile("cp.async.wait_group %0;" :: "n"(N) : "memory");
}
__device__ __forceinline__ void cpasync_commit() {
    asm volatile("cp.async.commit_group;" ::: "memory");
}
__device__ __forceinline__ void cpasync16(uint32_t daddr, const void* gaddr) {
    asm volatile("cp.async.cg.shared.global [%0], [%1], 16;" :: "r"(daddr), "l"(gaddr) : "memory");
}
__device__ __forceinline__ void ldsm_x4(uint32_t& r0, uint32_t& r1, uint32_t& r2, uint32_t& r3,
                                        uint32_t addr) {
    asm volatile("ldmatrix.sync.aligned.m8n8.x4.shared.b16 {%0,%1,%2,%3}, [%4];"
                 : "=r"(r0), "=r"(r1), "=r"(r2), "=r"(r3) : "r"(addr));
}
__device__ __forceinline__ void mma16816(float* d, const uint32_t* a, const uint32_t* b) {
    asm volatile(
        "mma.sync.aligned.m16n8k16.row.col.f32.bf16.bf16.f32 "
        "{%0,%1,%2,%3}, {%4,%5,%6,%7}, {%8,%9}, {%0,%1,%2,%3};"
        : "+f"(d[0]), "+f"(d[1]), "+f"(d[2]), "+f"(d[3])
        : "r"(a[0]), "r"(a[1]), "r"(a[2]), "r"(a[3]), "r"(b[0]), "r"(b[1]));
}
// order-preserving float<->uint for atomicMax on floats
__device__ __forceinline__ unsigned f2o(float f) {
    unsigned u = __float_as_uint(f);
    return u ^ ((u >> 31) ? 0xFFFFFFFFu : 0x80000000u);
}
__device__ __forceinline__ float o2f(unsigned u) {
    u = (u >> 31) ? (u ^ 0x80000000u) : ~u;
    return __uint_as_float(u);
}
__device__ __forceinline__ float lrelu(float x) { return x > 0.f ? x : 0.2f * x; }

// ---------------- bf16 hi/lo split converts (x and W fused) ----------------
__global__ void k_cvt(const float* __restrict__ x, const float* __restrict__ W) {
    int i = blockIdx.x * blockDim.x + threadIdx.x;
    if (i < N_NODES * IN_CH) {
        int n = i / IN_CH, k = i % IN_CH;
        float v = x[i];
        __nv_bfloat16 hi = __float2bfloat16(v);
        __nv_bfloat16 lo = __float2bfloat16(v - __bfloat162float(hi));
        size_t base = (size_t)n * KP;
        g_xa[base + k] = hi;
        g_xa[base + 256 + k] = hi;
        g_xa[base + 512 + k] = lo;
    }
    if (i < IN_CH * F1) {
        int k = i / F1, n = i % F1;
        float v = W[i];
        __nv_bfloat16 hi = __float2bfloat16(v);
        __nv_bfloat16 lo = __float2bfloat16(v - __bfloat162float(hi));
        size_t base = (size_t)n * KP;
        g_wb[base + k] = hi;
        g_wb[base + 256 + k] = lo;
        g_wb[base + 512 + k] = hi;
    }
}

// ---------------- init: deg, gmax, dtype detect (warp-parallel) ----------------
__global__ void k_init(const int* __restrict__ ei32) {
    int i = blockIdx.x * blockDim.x + threadIdx.x;
    if (i <= N_NODES) g_deg[i] = (i < N_NODES) ? 1 : 0;   // 1 = self loop
    if (i < HEADS) g_gmax1[i] = 0u;
    if (i == HEADS) g_gmax2 = 0u;
    if (blockIdx.x == 0 && threadIdx.x < 32) {
        int v = ei32[2 * threadIdx.x + 1] | ei32[2 * (threadIdx.x + 32) + 1];
        unsigned b = __ballot_sync(0xffffffffu, v != 0);
        if (threadIdx.x == 0) g_is64 = (b == 0) ? 1 : 0;
    }
}
__device__ __forceinline__ int load_idx(const void* __restrict__ ei, int pos) {
    int v;
    if (g_is64) v = (int)((const long long*)ei)[pos];
    else        v = ((const int*)ei)[pos];
    return v < 0 ? 0 : (v >= N_NODES ? N_NODES - 1 : v);
}

// ---------------- CSR build ----------------
__global__ void k_hist(const void* __restrict__ ei) {
    int i = blockIdx.x * blockDim.x + threadIdx.x;
    if (i < N_EDGES) atomicAdd(&g_deg[load_idx(ei, N_EDGES + i)], 1);
}
__global__ void k_scanA() {
    __shared__ int ss[256];
    int t = threadIdx.x, i = blockIdx.x * 256 + t;
    int v = (i < N_NODES) ? g_deg[i] : 0;
    ss[t] = v; __syncthreads();
    for (int o = 1; o < 256; o <<= 1) {
        int u = (t >= o) ? ss[t - o] : 0; __syncthreads();
        ss[t] += u; __syncthreads();
    }
    if (t == 255) g_bsum[blockIdx.x] = ss[255];
}
__global__ void k_scanB() {
    __shared__ int ss[256];
    int t = threadIdx.x;
    int v = (t < NSCB) ? g_bsum[t] : 0;
    ss[t] = v; __syncthreads();
    for (int o = 1; o < 256; o <<= 1) {
        int u = (t >= o) ? ss[t - o] : 0; __syncthreads();
        ss[t] += u; __syncthreads();
    }
    if (t < NSCB) g_bbase[t] = ss[t] - v;
    if (t == 255) g_off[N_NODES] = ss[255];
}
__global__ void k_scanC() {
    __shared__ int ss[256];
    int t = threadIdx.x, i = blockIdx.x * 256 + t;
    int v = (i < N_NODES) ? g_deg[i] : 0;
    ss[t] = v; __syncthreads();
    for (int o = 1; o < 256; o <<= 1) {
        int u = (t >= o) ? ss[t - o] : 0; __syncthreads();
        ss[t] += u; __syncthreads();
    }
    if (i < N_NODES) {
        int off = g_bbase[blockIdx.x] + ss[t] - v;
        g_off[i] = off;
        g_cur[i] = off;
    }
}
__global__ void k_scatter(const void* __restrict__ ei) {
    int i = blockIdx.x * blockDim.x + threadIdx.x;
    if (i >= ET) return;
    int s, d;
    if (i < N_EDGES) { s = load_idx(ei, i); d = load_idx(ei, N_EDGES + i); }
    else             { s = d = i - N_EDGES; }
    int slot = atomicAdd(&g_cur[d], 1);
    if (slot < ET) g_esrc[slot] = s;
}

// ---------------- GEMM1 via mma.sync bf16 (K'=768) + fused logits + gmax ----------------
// CTA 256x128, 512 threads (16 warps: 8m x 2n), warp tile 32x64. 12 K-chunks of 64 bf16.
// Stage = A(32KB) + B(16KB) = 48KB; double-buffered dynamic SMEM = 96KB. 1 CTA/SM.
#define CHUNKS 12
#define STAGE 49152

__device__ __forceinline__ void copy_chunk256(uint32_t st, int bm, int bn, int k0, int tid) {
#pragma unroll
    for (int it = 0; it < 6; it++) {
        int flat = it * 512 + tid;          // 0..3071 16B units
        if (flat < 2048) {                   // A: 256 rows x 8 units
            int r = flat >> 3, q = flat & 7;
            int m = bm + r; if (m >= N_NODES) m = N_NODES - 1;
            uint32_t sw = (uint32_t)(r * 8 + (q ^ (r & 7))) * 16;
            cpasync16(st + sw, (const char*)g_xa + ((size_t)m * KP + k0 + q * 8) * 2);
        } else {                             // B: 128 rows x 8 units
            int f2 = flat - 2048;
            int r = f2 >> 3, q = f2 & 7;
            uint32_t sw = (uint32_t)(r * 8 + (q ^ (r & 7))) * 16;
            cpasync16(st + 32768 + sw,
                      (const char*)g_wb + ((size_t)(bn * 128 + r) * KP + k0 + q * 8) * 2);
        }
    }
    cpasync_commit();
}

__global__ __launch_bounds__(512, 1) void k_gemm1_mma(const float* __restrict__ att_s,
                                                      const float* __restrict__ att_d) {
    extern __shared__ __align__(1024) char smem[];
    __shared__ float satt[256];
    const uint32_t sb = smem_u32(smem);
    const int tid = threadIdx.x, wid = tid >> 5, lane = tid & 31;
    const int warp_m = wid >> 1, warp_n = wid & 1;   // 8m x 2n
    const int bm = blockIdx.x * 256;
    const int bn = blockIdx.y;

    for (int i = tid; i < 128; i += 512) {
        satt[i]       = att_s[bn * 128 + i];
        satt[128 + i] = att_d[bn * 128 + i];
    }

    float d[2][8][4];
#pragma unroll
    for (int g = 0; g < 2; g++)
#pragma unroll
        for (int nf = 0; nf < 8; nf++)
#pragma unroll
            for (int q = 0; q < 4; q++) d[g][nf][q] = 0.f;

    copy_chunk256(sb, bm, bn, 0, tid);

    for (int ch = 0; ch < CHUNKS; ch++) {
        uint32_t curA = sb + (ch & 1) * STAGE;
        uint32_t curB = curA + 32768;
        if (ch + 1 < CHUNKS) {
            copy_chunk256(sb + ((ch + 1) & 1) * STAGE, bm, bn, (ch + 1) * 64, tid);
            cpasync_wait<1>();
        } else {
            cpasync_wait<0>();
        }
        __syncthreads();

#pragma unroll
        for (int ks = 0; ks < 4; ks++) {
            uint32_t a[2][4];
#pragma unroll
            for (int g = 0; g < 2; g++) {
                int rA = warp_m * 32 + g * 16 + (lane & 15);
                int u = ks * 2 + (lane >> 4);
                ldsm_x4(a[g][0], a[g][1], a[g][2], a[g][3],
                        curA + (uint32_t)(rA * 8 + (u ^ (rA & 7))) * 16);
            }
            uint32_t b[8][2];
#pragma unroll
            for (int nf2 = 0; nf2 < 4; nf2++) {
                int rB = warp_n * 64 + nf2 * 16 + (lane & 7) + ((lane >> 4) & 1) * 8;
                int u = ks * 2 + ((lane >> 3) & 1);
                ldsm_x4(b[nf2 * 2][0], b[nf2 * 2][1], b[nf2 * 2 + 1][0], b[nf2 * 2 + 1][1],
                        curB + (uint32_t)(rB * 8 + (u ^ (rB & 7))) * 16);
            }
#pragma unroll
            for (int g = 0; g < 2; g++)
#pragma unroll
                for (int nf = 0; nf < 8; nf++)
                    mma16816(d[g][nf], a[g], b[nf]);
        }
        __syncthreads();
    }

    // epilogue: fused logits (head = bn*2 + warp_n) + h1 stores + global a_src max
    const int head = bn * 2 + warp_n;
    float mx = -1e30f;
#pragma unroll
    for (int g = 0; g < 2; g++) {
        float sl0 = 0.f, sl1 = 0.f, dl0 = 0.f, dl1 = 0.f;
        int r0 = bm + warp_m * 32 + g * 16 + (lane >> 2);
        bool ok0 = r0 < N_NODES, ok1 = (r0 + 8) < N_NODES;
#pragma unroll
        for (int nf = 0; nf < 8; nf++) {
            int j = warp_n * 64 + nf * 8 + 2 * (lane & 3);
            float a0 = satt[j], a1 = satt[j + 1];
            float c0 = satt[128 + j], c1 = satt[128 + j + 1];
            float v0 = d[g][nf][0], v1 = d[g][nf][1];
            float v2 = d[g][nf][2], v3 = d[g][nf][3];
            sl0 += v0 * a0 + v1 * a1;  dl0 += v0 * c0 + v1 * c1;
            sl1 += v2 * a0 + v3 * a1;  dl1 += v2 * c0 + v3 * c1;
            size_t cb = (size_t)bn * 128 + j;
            if (ok0) *(float2*)&g_h1[(size_t)r0 * F1 + cb] = make_float2(v0, v1);
            if (ok1) *(float2*)&g_h1[(size_t)(r0 + 8) * F1 + cb] = make_float2(v2, v3);
        }
        sl0 += __shfl_xor_sync(0xffffffffu, sl0, 1); sl0 += __shfl_xor_sync(0xffffffffu, sl0, 2);
        sl1 += __shfl_xor_sync(0xffffffffu, sl1, 1); sl1 += __shfl_xor_sync(0xffffffffu, sl1, 2);
        dl0 += __shfl_xor_sync(0xffffffffu, dl0, 1); dl0 += __shfl_xor_sync(0xffffffffu, dl0, 2);
        dl1 += __shfl_xor_sync(0xffffffffu, dl1, 1); dl1 += __shfl_xor_sync(0xffffffffu, dl1, 2);
        if (ok0) mx = fmaxf(mx, sl0);
        if (ok1) mx = fmaxf(mx, sl1);
        if ((lane & 3) == 0) {
            if (ok0) { g_as1[r0 * HEADS + head] = sl0; g_ad1[r0 * HEADS + head] = dl0; }
            if (ok1) { g_as1[(r0 + 8) * HEADS + head] = sl1; g_ad1[(r0 + 8) * HEADS + head] = dl1; }
        }
    }
#pragma unroll
    for (int off = 16; off >= 1; off >>= 1)
        mx = fmaxf(mx, __shfl_xor_sync(0xffffffffu, mx, off));
    if (lane == 0) atomicMax(&g_gmax1[head], f2o(mx));
}

// ---------------- layer-1 aggregation (no max pass; pipelined) ----------------
__global__ void k_agg1(const float* __restrict__ b1) {
    int n = (blockIdx.x * blockDim.x + threadIdx.x) >> 5;
    int lane = threadIdx.x & 31;
    if (n >= N_NODES) return;
    const int o0 = g_off[n], o1 = g_off[n + 1];
    const int head = lane >> 2;
    const float myadn = g_ad1[n * HEADS + head];
    const float m = lrelu(o2f(g_gmax1[head]) + myadn);   // upper bound of all edge logits

    float denom = 0.f;
    float acc[16];
#pragma unroll
    for (int q = 0; q < 16; q++) acc[q] = 0.f;

    // pipelined: src index 2 ahead, logits + data 1 ahead
    int s1 = g_esrc[o0];
    int s2 = (o0 + 1 < o1) ? g_esrc[o0 + 1] : s1;
    float a_cur = g_as1[(size_t)s1 * HEADS + head];
    const float4* p = (const float4*)(g_h1 + (size_t)s1 * F1) + lane * 4;
    float4 t0 = p[0], t1 = p[1], t2 = p[2], t3 = p[3];
    s1 = s2;

    for (int e = o0; e < o1; e++) {
        int s3 = (e + 2 < o1) ? g_esrc[e + 2] : s1;
        float a_nxt = 0.f;
        float4 u0, u1, u2, u3;
        if (e + 1 < o1) {
            a_nxt = g_as1[(size_t)s1 * HEADS + head];
            const float4* q = (const float4*)(g_h1 + (size_t)s1 * F1) + lane * 4;
            u0 = q[0]; u1 = q[1]; u2 = q[2]; u3 = q[3];
        } else {
            u0 = u1 = u2 = u3 = make_float4(0.f, 0.f, 0.f, 0.f);
        }
        float w = __expf(lrelu(a_cur + myadn) - m);
        denom += w;
        acc[0]  = fmaf(w, t0.x, acc[0]);  acc[1]  = fmaf(w, t0.y, acc[1]);
        acc[2]  = fmaf(w, t0.z, acc[2]);  acc[3]  = fmaf(w, t0.w, acc[3]);
        acc[4]  = fmaf(w, t1.x, acc[4]);  acc[5]  = fmaf(w, t1.y, acc[5]);
        acc[6]  = fmaf(w, t1.z, acc[6]);  acc[7]  = fmaf(w, t1.w, acc[7]);
        acc[8]  = fmaf(w, t2.x, acc[8]);  acc[9]  = fmaf(w, t2.y, acc[9]);
        acc[10] = fmaf(w, t2.z, acc[10]); acc[11] = fmaf(w, t2.w, acc[11]);
        acc[12] = fmaf(w, t3.x, acc[12]); acc[13] = fmaf(w, t3.y, acc[13]);
        acc[14] = fmaf(w, t3.z, acc[14]); acc[15] = fmaf(w, t3.w, acc[15]);
        s1 = s3; a_cur = a_nxt;
        t0 = u0; t1 = u1; t2 = u2; t3 = u3;
    }
    const float inv = 1.0f / (denom + 1e-16f);
    float4* outp = (float4*)(g_h2 + (size_t)n * F1) + lane * 4;
#pragma unroll
    for (int q = 0; q < 4; q++) {
        float4 bq = ((const float4*)b1)[lane * 4 + q];
        float4 r;
        float x0 = acc[q * 4 + 0] * inv + bq.x;
        float x1 = acc[q * 4 + 1] * inv + bq.y;
        float x2 = acc[q * 4 + 2] * inv + bq.z;
        float x3 = acc[q * 4 + 3] * inv + bq.w;
        r.x = x0 > 0.f ? x0 : (__expf(x0) - 1.f);
        r.y = x1 > 0.f ? x1 : (__expf(x1) - 1.f);
        r.z = x2 > 0.f ? x2 : (__expf(x2) - 1.f);
        r.w = x3 > 0.f ? x3 : (__expf(x3) - 1.f);
        outp[q] = r;
    }
}

// ---------------- GEMM2 (h2 @ W2, 512->16) + layer-2 logits + gmax ----------------
__global__ __launch_bounds__(256) void k_gemm2(const float* __restrict__ W2,
                                               const float* __restrict__ att_s2,
                                               const float* __restrict__ att_d2) {
    __shared__ __align__(16) float sW[F1 * OUT_CH];
    __shared__ float sAs[OUT_CH], sAd[OUT_CH];
    int tid = threadIdx.x;
    for (int i = tid; i < F1 * OUT_CH / 4; i += 256)
        ((float4*)sW)[i] = ((const float4*)W2)[i];
    if (tid < OUT_CH) { sAs[tid] = att_s2[tid]; sAd[tid] = att_d2[tid]; }
    __syncthreads();
    int n = blockIdx.x * 16 + tid / 16;
    int c = tid % 16;
    if (n >= N_NODES) return;
    const float4* row = (const float4*)(g_h2 + (size_t)n * F1);
    float acc = 0.f;
#pragma unroll 8
    for (int k4 = 0; k4 < F1 / 4; k4++) {
        float4 v = row[k4];
        int k = k4 * 4;
        acc = fmaf(v.x, sW[(k + 0) * OUT_CH + c], acc);
        acc = fmaf(v.y, sW[(k + 1) * OUT_CH + c], acc);
        acc = fmaf(v.z, sW[(k + 2) * OUT_CH + c], acc);
        acc = fmaf(v.w, sW[(k + 3) * OUT_CH + c], acc);
    }
    g_t2[n * OUT_CH + c] = acc;
    float ls = acc * sAs[c];
    float ld_ = acc * sAd[c];
#pragma unroll
    for (int off = 8; off >= 1; off >>= 1) {
        ls  += __shfl_xor_sync(0xffffffffu, ls, off);
        ld_ += __shfl_xor_sync(0xffffffffu, ld_, off);
    }
    if (c == 0) { g_as2[n] = ls; g_ad2[n] = ld_; }
    float mx = fmaxf(ls, __shfl_xor_sync(0xffffffffu, ls, 16));
    if ((tid & 31) == 0) atomicMax(&g_gmax2, f2o(mx));
}

// ---------------- layer-2 aggregation (no max pass; pipelined) + log_softmax ----------------
__global__ void k_agg2(const float* __restrict__ b2, float* __restrict__ out) {
    int n = (blockIdx.x * blockDim.x + threadIdx.x) >> 5;
    int lane = threadIdx.x & 31;
    if (n >= N_NODES) return;
    const int o0 = g_off[n], o1 = g_off[n + 1];
    const float adn = g_ad2[n];
    const float m = lrelu(o2f(g_gmax2) + adn);

    float denom = 0.f, acc = 0.f;
    int c = lane & 15;

    int s1 = g_esrc[o0];
    int s2 = (o0 + 1 < o1) ? g_esrc[o0 + 1] : s1;
    float a_cur = g_as2[s1];
    float t_cur = g_t2[(size_t)s1 * OUT_CH + c];
    s1 = s2;

    for (int e = o0; e < o1; e++) {
        int s3 = (e + 2 < o1) ? g_esrc[e + 2] : s1;
        float a_nxt = 0.f, t_nxt = 0.f;
        if (e + 1 < o1) {
            a_nxt = g_as2[s1];
            t_nxt = g_t2[(size_t)s1 * OUT_CH + c];
        }
        float w = __expf(lrelu(a_cur + adn) - m);
        denom += w;
        acc = fmaf(w, t_cur, acc);
        s1 = s3; a_cur = a_nxt; t_cur = t_nxt;
    }
    float o = acc / (denom + 1e-16f) + b2[c];
    float mx = o;
#pragma unroll
    for (int off = 8; off >= 1; off >>= 1)
        mx = fmaxf(mx, __shfl_xor_sync(0xffffffffu, mx, off));
    float ex = __expf(o - mx);
    float sm = ex;
#pragma unroll
    for (int off = 8; off >= 1; off >>= 1)
        sm += __shfl_xor_sync(0xffffffffu, sm, off);
    float res = o - mx - logf(sm);
    if (lane < 16) out[(size_t)n * OUT_CH + lane] = res;
}

// ---------------- launch ----------------
extern "C" void kernel_launch(void* const* d_in, const int* in_sizes, int n_in,
                              void* d_out, int out_size) {
    const float* x    = (const float*)d_in[0];
    const void*  ei   = d_in[1];
    const float* W1   = (const float*)d_in[2];
    const float* as1  = (const float*)d_in[3];
    const float* ad1  = (const float*)d_in[4];
    const float* b1   = (const float*)d_in[5];
    const float* W2   = (const float*)d_in[6];
    const float* as2  = (const float*)d_in[7];
    const float* ad2  = (const float*)d_in[8];
    const float* b2   = (const float*)d_in[9];
    float* out = (float*)d_out;

    cudaFuncSetAttribute(k_gemm1_mma, cudaFuncAttributeMaxDynamicSharedMemorySize, 2 * STAGE);

    // order chosen so k_gemm1_mma is launch #4 (ncu capture slot in R9/R10)
    k_cvt<<<(N_NODES * IN_CH + 255) / 256, 256>>>(x, W1);
    k_init<<<(N_NODES + 256) / 256, 256>>>((const int*)ei);
    k_hist<<<(N_EDGES + 255) / 256, 256>>>(ei);

    dim3 g1((N_NODES + 255) / 256, 4);
    k_gemm1_mma<<<g1, 512, 2 * STAGE>>>(as1, ad1);

    k_scanA<<<NSCB, 256>>>();
    k_scanB<<<1, 256>>>();
    k_scanC<<<NSCB, 256>>>();
    k_scatter<<<(ET + 255) / 256, 256>>>(ei);

    k_agg1<<<(N_NODES + 7) / 8, 256>>>(b1);

    k_gemm2<<<N_NODES / 16, 256>>>(W2, as2, ad2);
    k_agg2<<<(N_NODES + 7) / 8, 256>>>(b2, out);
}

// round 13
// speedup vs baseline: 1.2706x; 1.2706x over previous
#include <cuda_runtime.h>
#include <cuda_bf16.h>
#include <cuda_fp16.h>
#include <cstdint>
#include <math.h>

#define N_NODES 50000
#define N_EDGES 500000
#define ET (N_EDGES + N_NODES)   // with self loops
#define IN_CH 256
#define F1 512                   // 8 heads * 64
#define HID 64
#define HEADS 8
#define OUT_CH 16
#define KP 768                   // K' = 3*256 for hi/lo-split bf16 GEMM

// ---------------- scratch (device globals; no allocation allowed) ----------------
__device__ __align__(16) __half g_h1h[(size_t)N_NODES * F1];   // x @ W1 (fp16, L2-resident)
__device__ __align__(16) float g_h2[(size_t)N_NODES * F1];     // layer-1 output (post ELU)
__device__ __align__(16) float g_as1[N_NODES * HEADS];
__device__ __align__(16) float g_ad1[N_NODES * HEADS];
__device__ __align__(16) float g_t2[N_NODES * OUT_CH];         // h2 @ W2
__device__ __align__(16) float g_as2[N_NODES];
__device__ __align__(16) float g_ad2[N_NODES];
__device__ __align__(16) __nv_bfloat16 g_xa[(size_t)N_NODES * KP];  // [xhi | xhi | xlo]
__device__ __align__(16) __nv_bfloat16 g_wb[(size_t)F1 * KP];       // per-out-col rows [Whi | Wlo | Whi]
__device__ int      g_deg[N_NODES + 1];
__device__ int      g_off[N_NODES + 1];
__device__ int      g_cur[N_NODES];
__device__ int      g_esrc[ET];                  // src id per dst-sorted edge
__device__ int      g_is64;
__device__ unsigned g_gmax1[HEADS];              // order-uint global max of as1 per head
__device__ unsigned g_gmax2;                     // order-uint global max of as2
#define NSCB 196                                 // ceil(50000/256)
__device__ int   g_bsum[NSCB];
__device__ int   g_bbase[NSCB];

// ---------------- helpers ----------------
__device__ __forceinline__ uint32_t smem_u32(const void* p) {
    uint32_t a;
    asm("{ .reg .u64 t; cvta.to.shared.u64 t, %1; cvt.u32.u64 %0, t; }" : "=r"(a) : "l"(p));
    return a;
}
template <int N>
__device__ __forceinline__ void cpasync_wait() {
    asm volatile("cp.async.wait_group %0;" :: "n"(N) : "memory");
}
__device__ __forceinline__ void cpasync_commit() {
    asm volatile("cp.async.commit_group;" ::: "memory");
}
__device__ __forceinline__ void cpasync16(uint32_t daddr, const void* gaddr) {
    asm volatile("cp.async.cg.shared.global [%0], [%1], 16;" :: "r"(daddr), "l"(gaddr) : "memory");
}
__device__ __forceinline__ void ldsm_x4(uint32_t& r0, uint32_t& r1, uint32_t& r2, uint32_t& r3,
                                        uint32_t addr) {
    asm volatile("ldmatrix.sync.aligned.m8n8.x4.shared.b16 {%0,%1,%2,%3}, [%4];"
                 : "=r"(r0), "=r"(r1), "=r"(r2), "=r"(r3) : "r"(addr));
}
__device__ __forceinline__ void mma16816(float* d, const uint32_t* a, const uint32_t* b) {
    asm volatile(
        "mma.sync.aligned.m16n8k16.row.col.f32.bf16.bf16.f32 "
        "{%0,%1,%2,%3}, {%4,%5,%6,%7}, {%8,%9}, {%0,%1,%2,%3};"
        : "+f"(d[0]), "+f"(d[1]), "+f"(d[2]), "+f"(d[3])
        : "r"(a[0]), "r"(a[1]), "r"(a[2]), "r"(a[3]), "r"(b[0]), "r"(b[1]));
}
// order-preserving float<->uint for atomicMax on floats
__device__ __forceinline__ unsigned f2o(float f) {
    unsigned u = __float_as_uint(f);
    return u ^ ((u >> 31) ? 0xFFFFFFFFu : 0x80000000u);
}
__device__ __forceinline__ float o2f(unsigned u) {
    u = (u >> 31) ? (u ^ 0x80000000u) : ~u;
    return __uint_as_float(u);
}
__device__ __forceinline__ float lrelu(float x) { return x > 0.f ? x : 0.2f * x; }

// ---------------- bf16 hi/lo split converts (x and W fused) ----------------
__global__ void k_cvt(const float* __restrict__ x, const float* __restrict__ W) {
    int i = blockIdx.x * blockDim.x + threadIdx.x;
    if (i < N_NODES * IN_CH) {
        int n = i / IN_CH, k = i % IN_CH;
        float v = x[i];
        __nv_bfloat16 hi = __float2bfloat16(v);
        __nv_bfloat16 lo = __float2bfloat16(v - __bfloat162float(hi));
        size_t base = (size_t)n * KP;
        g_xa[base + k] = hi;
        g_xa[base + 256 + k] = hi;
        g_xa[base + 512 + k] = lo;
    }
    if (i < IN_CH * F1) {
        int k = i / F1, n = i % F1;
        float v = W[i];
        __nv_bfloat16 hi = __float2bfloat16(v);
        __nv_bfloat16 lo = __float2bfloat16(v - __bfloat162float(hi));
        size_t base = (size_t)n * KP;
        g_wb[base + k] = hi;
        g_wb[base + 256 + k] = lo;
        g_wb[base + 512 + k] = hi;
    }
}

// ---------------- init: deg, gmax, dtype detect (warp-parallel) ----------------
__global__ void k_init(const int* __restrict__ ei32) {
    int i = blockIdx.x * blockDim.x + threadIdx.x;
    if (i <= N_NODES) g_deg[i] = (i < N_NODES) ? 1 : 0;   // 1 = self loop
    if (i < HEADS) g_gmax1[i] = 0u;
    if (i == HEADS) g_gmax2 = 0u;
    if (blockIdx.x == 0 && threadIdx.x < 32) {
        int v = ei32[2 * threadIdx.x + 1] | ei32[2 * (threadIdx.x + 32) + 1];
        unsigned b = __ballot_sync(0xffffffffu, v != 0);
        if (threadIdx.x == 0) g_is64 = (b == 0) ? 1 : 0;
    }
}
__device__ __forceinline__ int load_idx(const void* __restrict__ ei, int pos) {
    int v;
    if (g_is64) v = (int)((const long long*)ei)[pos];
    else        v = ((const int*)ei)[pos];
    return v < 0 ? 0 : (v >= N_NODES ? N_NODES - 1 : v);
}

// ---------------- CSR build ----------------
__global__ void k_hist(const void* __restrict__ ei) {
    int i = blockIdx.x * blockDim.x + threadIdx.x;
    if (i < N_EDGES) atomicAdd(&g_deg[load_idx(ei, N_EDGES + i)], 1);
}
__global__ void k_scanA() {
    __shared__ int ss[256];
    int t = threadIdx.x, i = blockIdx.x * 256 + t;
    int v = (i < N_NODES) ? g_deg[i] : 0;
    ss[t] = v; __syncthreads();
    for (int o = 1; o < 256; o <<= 1) {
        int u = (t >= o) ? ss[t - o] : 0; __syncthreads();
        ss[t] += u; __syncthreads();
    }
    if (t == 255) g_bsum[blockIdx.x] = ss[255];
}
__global__ void k_scanB() {
    __shared__ int ss[256];
    int t = threadIdx.x;
    int v = (t < NSCB) ? g_bsum[t] : 0;
    ss[t] = v; __syncthreads();
    for (int o = 1; o < 256; o <<= 1) {
        int u = (t >= o) ? ss[t - o] : 0; __syncthreads();
        ss[t] += u; __syncthreads();
    }
    if (t < NSCB) g_bbase[t] = ss[t] - v;
    if (t == 255) g_off[N_NODES] = ss[255];
}
__global__ void k_scanC() {
    __shared__ int ss[256];
    int t = threadIdx.x, i = blockIdx.x * 256 + t;
    int v = (i < N_NODES) ? g_deg[i] : 0;
    ss[t] = v; __syncthreads();
    for (int o = 1; o < 256; o <<= 1) {
        int u = (t >= o) ? ss[t - o] : 0; __syncthreads();
        ss[t] += u; __syncthreads();
    }
    if (i < N_NODES) {
        int off = g_bbase[blockIdx.x] + ss[t] - v;
        g_off[i] = off;
        g_cur[i] = off;
    }
}
__global__ void k_scatter(const void* __restrict__ ei) {
    int i = blockIdx.x * blockDim.x + threadIdx.x;
    if (i >= ET) return;
    int s, d;
    if (i < N_EDGES) { s = load_idx(ei, i); d = load_idx(ei, N_EDGES + i); }
    else             { s = d = i - N_EDGES; }
    int slot = atomicAdd(&g_cur[d], 1);
    if (slot < ET) g_esrc[slot] = s;
}

// ---------------- GEMM1 via mma.sync bf16 (K'=768) + fused logits + gmax ----------------
// CTA 128x128, 8 warps (4m x 2n), warp tile 32x64. 12 K-chunks of 64 bf16. (R10 config)
#define CHUNKS 12

__device__ __forceinline__ void copy_chunk(uint32_t sA, uint32_t sB, int bm, int bn,
                                           int k0, int tid) {
#pragma unroll
    for (int it = 0; it < 4; it++) {
        int flat = it * 256 + tid;      // 0..1023 16B units
        int r = flat >> 3, q = flat & 7;
        int m = bm + r; if (m >= N_NODES) m = N_NODES - 1;
        uint32_t sw = (uint32_t)(r * 8 + (q ^ (r & 7))) * 16;
        cpasync16(sA + sw, (const char*)g_xa + ((size_t)m * KP + k0 + q * 8) * 2);
        cpasync16(sB + sw, (const char*)g_wb + ((size_t)(bn * 128 + r) * KP + k0 + q * 8) * 2);
    }
    cpasync_commit();
}

__global__ __launch_bounds__(256) void k_gemm1_mma(const float* __restrict__ att_s,
                                                   const float* __restrict__ att_d) {
    extern __shared__ __align__(1024) char smem[];
    __shared__ float satt[256];
    const uint32_t sb = smem_u32(smem);
    const int tid = threadIdx.x, wid = tid >> 5, lane = tid & 31;
    const int warp_m = wid & 3, warp_n = wid >> 2;
    const int bm = blockIdx.x * 128;
    const int bn = blockIdx.y;

    for (int i = tid; i < 128; i += 256) {
        satt[i]       = att_s[bn * 128 + i];
        satt[128 + i] = att_d[bn * 128 + i];
    }

    float d[2][8][4];
#pragma unroll
    for (int g = 0; g < 2; g++)
#pragma unroll
        for (int nf = 0; nf < 8; nf++)
#pragma unroll
            for (int q = 0; q < 4; q++) d[g][nf][q] = 0.f;

    copy_chunk(sb, sb + 16384, bm, bn, 0, tid);

    for (int ch = 0; ch < CHUNKS; ch++) {
        uint32_t curA = sb + (ch & 1) * 32768;
        uint32_t curB = curA + 16384;
        if (ch + 1 < CHUNKS) {
            copy_chunk(sb + ((ch + 1) & 1) * 32768, sb + ((ch + 1) & 1) * 32768 + 16384,
                       bm, bn, (ch + 1) * 64, tid);
            cpasync_wait<1>();
        } else {
            cpasync_wait<0>();
        }
        __syncthreads();

#pragma unroll
        for (int ks = 0; ks < 4; ks++) {
            uint32_t a[2][4];
#pragma unroll
            for (int g = 0; g < 2; g++) {
                int rA = warp_m * 32 + g * 16 + (lane & 15);
                int u = ks * 2 + (lane >> 4);
                ldsm_x4(a[g][0], a[g][1], a[g][2], a[g][3],
                        curA + (uint32_t)(rA * 8 + (u ^ (rA & 7))) * 16);
            }
            uint32_t b[8][2];
#pragma unroll
            for (int nf2 = 0; nf2 < 4; nf2++) {
                int rB = warp_n * 64 + nf2 * 16 + (lane & 7) + ((lane >> 4) & 1) * 8;
                int u = ks * 2 + ((lane >> 3) & 1);
                ldsm_x4(b[nf2 * 2][0], b[nf2 * 2][1], b[nf2 * 2 + 1][0], b[nf2 * 2 + 1][1],
                        curB + (uint32_t)(rB * 8 + (u ^ (rB & 7))) * 16);
            }
#pragma unroll
            for (int g = 0; g < 2; g++)
#pragma unroll
                for (int nf = 0; nf < 8; nf++)
                    mma16816(d[g][nf], a[g], b[nf]);
        }
        __syncthreads();
    }

    // epilogue: fused logits (head = bn*2 + warp_n) + h1 (fp16) stores + global a_src max
    const int head = bn * 2 + warp_n;
    float mx = -1e30f;
#pragma unroll
    for (int g = 0; g < 2; g++) {
        float sl0 = 0.f, sl1 = 0.f, dl0 = 0.f, dl1 = 0.f;
        int r0 = bm + warp_m * 32 + g * 16 + (lane >> 2);
        bool ok0 = r0 < N_NODES, ok1 = (r0 + 8) < N_NODES;
#pragma unroll
        for (int nf = 0; nf < 8; nf++) {
            int j = warp_n * 64 + nf * 8 + 2 * (lane & 3);
            float a0 = satt[j], a1 = satt[j + 1];
            float c0 = satt[128 + j], c1 = satt[128 + j + 1];
            float v0 = d[g][nf][0], v1 = d[g][nf][1];
            float v2 = d[g][nf][2], v3 = d[g][nf][3];
            sl0 += v0 * a0 + v1 * a1;  dl0 += v0 * c0 + v1 * c1;
            sl1 += v2 * a0 + v3 * a1;  dl1 += v2 * c0 + v3 * c1;
            size_t cb = (size_t)bn * 128 + j;
            if (ok0) *(__half2*)&g_h1h[(size_t)r0 * F1 + cb] = __floats2half2_rn(v0, v1);
            if (ok1) *(__half2*)&g_h1h[(size_t)(r0 + 8) * F1 + cb] = __floats2half2_rn(v2, v3);
        }
        sl0 += __shfl_xor_sync(0xffffffffu, sl0, 1); sl0 += __shfl_xor_sync(0xffffffffu, sl0, 2);
        sl1 += __shfl_xor_sync(0xffffffffu, sl1, 1); sl1 += __shfl_xor_sync(0xffffffffu, sl1, 2);
        dl0 += __shfl_xor_sync(0xffffffffu, dl0, 1); dl0 += __shfl_xor_sync(0xffffffffu, dl0, 2);
        dl1 += __shfl_xor_sync(0xffffffffu, dl1, 1); dl1 += __shfl_xor_sync(0xffffffffu, dl1, 2);
        if (ok0) mx = fmaxf(mx, sl0);
        if (ok1) mx = fmaxf(mx, sl1);
        if ((lane & 3) == 0) {
            if (ok0) { g_as1[r0 * HEADS + head] = sl0; g_ad1[r0 * HEADS + head] = dl0; }
            if (ok1) { g_as1[(r0 + 8) * HEADS + head] = sl1; g_ad1[(r0 + 8) * HEADS + head] = dl1; }
        }
    }
#pragma unroll
    for (int off = 16; off >= 1; off >>= 1)
        mx = fmaxf(mx, __shfl_xor_sync(0xffffffffu, mx, off));
    if (lane == 0) atomicMax(&g_gmax1[head], f2o(mx));
}

// ---------------- layer-1 aggregation (fp16 gather, no max pass, pipelined) ----------------
__global__ void k_agg1(const float* __restrict__ b1) {
    int n = (blockIdx.x * blockDim.x + threadIdx.x) >> 5;
    int lane = threadIdx.x & 31;
    if (n >= N_NODES) return;
    const int o0 = g_off[n], o1 = g_off[n + 1];
    const int head = lane >> 2;
    const float myadn = g_ad1[n * HEADS + head];
    const float m = lrelu(o2f(g_gmax1[head]) + myadn);   // upper bound of all edge logits

    float denom = 0.f;
    float acc[16];
#pragma unroll
    for (int q = 0; q < 16; q++) acc[q] = 0.f;

    // pipelined: src index 2 ahead, logits + data 1 ahead. lane owns halves [lane*16, lane*16+16)
    int s1 = g_esrc[o0];
    int s2 = (o0 + 1 < o1) ? g_esrc[o0 + 1] : s1;
    float a_cur = g_as1[(size_t)s1 * HEADS + head];
    const uint4* p = (const uint4*)(g_h1h + (size_t)s1 * F1) + lane * 2;
    uint4 t0 = p[0], t1 = p[1];
    s1 = s2;

    for (int e = o0; e < o1; e++) {
        int s3 = (e + 2 < o1) ? g_esrc[e + 2] : s1;
        float a_nxt = 0.f;
        uint4 u0, u1;
        if (e + 1 < o1) {
            a_nxt = g_as1[(size_t)s1 * HEADS + head];
            const uint4* q = (const uint4*)(g_h1h + (size_t)s1 * F1) + lane * 2;
            u0 = q[0]; u1 = q[1];
        } else {
            u0 = make_uint4(0, 0, 0, 0); u1 = u0;
        }
        float w = __expf(lrelu(a_cur + myadn) - m);
        denom += w;
        const __half2* hp = (const __half2*)&t0;
#pragma unroll
        for (int q2 = 0; q2 < 4; q2++) {
            float2 f = __half22float2(hp[q2]);
            acc[2 * q2]     = fmaf(w, f.x, acc[2 * q2]);
            acc[2 * q2 + 1] = fmaf(w, f.y, acc[2 * q2 + 1]);
        }
        const __half2* hq = (const __half2*)&t1;
#pragma unroll
        for (int q2 = 0; q2 < 4; q2++) {
            float2 f = __half22float2(hq[q2]);
            acc[8 + 2 * q2]     = fmaf(w, f.x, acc[8 + 2 * q2]);
            acc[8 + 2 * q2 + 1] = fmaf(w, f.y, acc[8 + 2 * q2 + 1]);
        }
        s1 = s3; a_cur = a_nxt;
        t0 = u0; t1 = u1;
    }
    const float inv = 1.0f / (denom + 1e-16f);
    float4* outp = (float4*)(g_h2 + (size_t)n * F1) + lane * 4;
#pragma unroll
    for (int q = 0; q < 4; q++) {
        float4 bq = ((const float4*)b1)[lane * 4 + q];
        float4 r;
        float x0 = acc[q * 4 + 0] * inv + bq.x;
        float x1 = acc[q * 4 + 1] * inv + bq.y;
        float x2 = acc[q * 4 + 2] * inv + bq.z;
        float x3 = acc[q * 4 + 3] * inv + bq.w;
        r.x = x0 > 0.f ? x0 : (__expf(x0) - 1.f);
        r.y = x1 > 0.f ? x1 : (__expf(x1) - 1.f);
        r.z = x2 > 0.f ? x2 : (__expf(x2) - 1.f);
        r.w = x3 > 0.f ? x3 : (__expf(x3) - 1.f);
        outp[q] = r;
    }
}

// ---------------- GEMM2 (h2 @ W2, 512->16) + layer-2 logits + gmax ----------------
__global__ __launch_bounds__(256) void k_gemm2(const float* __restrict__ W2,
                                               const float* __restrict__ att_s2,
                                               const float* __restrict__ att_d2) {
    __shared__ __align__(16) float sW[F1 * OUT_CH];
    __shared__ float sAs[OUT_CH], sAd[OUT_CH];
    int tid = threadIdx.x;
    for (int i = tid; i < F1 * OUT_CH / 4; i += 256)
        ((float4*)sW)[i] = ((const float4*)W2)[i];
    if (tid < OUT_CH) { sAs[tid] = att_s2[tid]; sAd[tid] = att_d2[tid]; }
    __syncthreads();
    int n = blockIdx.x * 16 + tid / 16;
    int c = tid % 16;
    if (n >= N_NODES) return;
    const float4* row = (const float4*)(g_h2 + (size_t)n * F1);
    float acc = 0.f;
#pragma unroll 8
    for (int k4 = 0; k4 < F1 / 4; k4++) {
        float4 v = row[k4];
        int k = k4 * 4;
        acc = fmaf(v.x, sW[(k + 0) * OUT_CH + c], acc);
        acc = fmaf(v.y, sW[(k + 1) * OUT_CH + c], acc);
        acc = fmaf(v.z, sW[(k + 2) * OUT_CH + c], acc);
        acc = fmaf(v.w, sW[(k + 3) * OUT_CH + c], acc);
    }
    g_t2[n * OUT_CH + c] = acc;
    float ls = acc * sAs[c];
    float ld_ = acc * sAd[c];
#pragma unroll
    for (int off = 8; off >= 1; off >>= 1) {
        ls  += __shfl_xor_sync(0xffffffffu, ls, off);
        ld_ += __shfl_xor_sync(0xffffffffu, ld_, off);
    }
    if (c == 0) { g_as2[n] = ls; g_ad2[n] = ld_; }
    float mx = fmaxf(ls, __shfl_xor_sync(0xffffffffu, ls, 16));
    if ((tid & 31) == 0) atomicMax(&g_gmax2, f2o(mx));
}

// ---------------- layer-2 aggregation (no max pass; pipelined) + log_softmax ----------------
__global__ void k_agg2(const float* __restrict__ b2, float* __restrict__ out) {
    int n = (blockIdx.x * blockDim.x + threadIdx.x) >> 5;
    int lane = threadIdx.x & 31;
    if (n >= N_NODES) return;
    const int o0 = g_off[n], o1 = g_off[n + 1];
    const float adn = g_ad2[n];
    const float m = lrelu(o2f(g_gmax2) + adn);

    float denom = 0.f, acc = 0.f;
    int c = lane & 15;

    int s1 = g_esrc[o0];
    int s2 = (o0 + 1 < o1) ? g_esrc[o0 + 1] : s1;
    float a_cur = g_as2[s1];
    float t_cur = g_t2[(size_t)s1 * OUT_CH + c];
    s1 = s2;

    for (int e = o0; e < o1; e++) {
        int s3 = (e + 2 < o1) ? g_esrc[e + 2] : s1;
        float a_nxt = 0.f, t_nxt = 0.f;
        if (e + 1 < o1) {
            a_nxt = g_as2[s1];
            t_nxt = g_t2[(size_t)s1 * OUT_CH + c];
        }
        float w = __expf(lrelu(a_cur + adn) - m);
        denom += w;
        acc = fmaf(w, t_cur, acc);
        s1 = s3; a_cur = a_nxt; t_cur = t_nxt;
    }
    float o = acc / (denom + 1e-16f) + b2[c];
    float mx = o;
#pragma unroll
    for (int off = 8; off >= 1; off >>= 1)
        mx = fmaxf(mx, __shfl_xor_sync(0xffffffffu, mx, off));
    float ex = __expf(o - mx);
    float sm = ex;
#pragma unroll
    for (int off = 8; off >= 1; off >>= 1)
        sm += __shfl_xor_sync(0xffffffffu, sm, off);
    float res = o - mx - logf(sm);
    if (lane < 16) out[(size_t)n * OUT_CH + lane] = res;
}

// ---------------- launch ----------------
extern "C" void kernel_launch(void* const* d_in, const int* in_sizes, int n_in,
                              void* d_out, int out_size) {
    const float* x    = (const float*)d_in[0];
    const void*  ei   = d_in[1];
    const float* W1   = (const float*)d_in[2];
    const float* as1  = (const float*)d_in[3];
    const float* ad1  = (const float*)d_in[4];
    const float* b1   = (const float*)d_in[5];
    const float* W2   = (const float*)d_in[6];
    const float* as2  = (const float*)d_in[7];
    const float* ad2  = (const float*)d_in[8];
    const float* b2   = (const float*)d_in[9];
    float* out = (float*)d_out;

    cudaFuncSetAttribute(k_gemm1_mma, cudaFuncAttributeMaxDynamicSharedMemorySize, 65536);

    k_cvt<<<(N_NODES * IN_CH + 255) / 256, 256>>>(x, W1);
    k_init<<<(N_NODES + 256) / 256, 256>>>((const int*)ei);
    k_hist<<<(N_EDGES + 255) / 256, 256>>>(ei);

    dim3 g1((N_NODES + 127) / 128, 4);
    k_gemm1_mma<<<g1, 256, 65536>>>(as1, ad1);

    k_scanA<<<NSCB, 256>>>();
    k_scanB<<<1, 256>>>();
    k_scanC<<<NSCB, 256>>>();
    k_scatter<<<(ET + 255) / 256, 256>>>(ei);

    k_agg1<<<(N_NODES + 7) / 8, 256>>>(b1);

    k_gemm2<<<N_NODES / 16, 256>>>(W2, as2, ad2);
    k_agg2<<<(N_NODES + 7) / 8, 256>>>(b2, out);
}

// round 14
// speedup vs baseline: 1.5830x; 1.2458x over previous
#include <cuda_runtime.h>
#include <cuda_bf16.h>
#include <cuda_fp16.h>
#include <cstdint>
#include <math.h>

#define N_NODES 50000
#define N_EDGES 500000
#define ET (N_EDGES + N_NODES)   // with self loops
#define IN_CH 256
#define F1 512                   // 8 heads * 64
#define HID 64
#define HEADS 8
#define OUT_CH 16
#define KP 512                   // K' = 2*256: xhi*(Whi) + xhi*(Wlo) = xhi*W

// ---------------- scratch (device globals; no allocation allowed) ----------------
__device__ __align__(16) __half g_h1h[(size_t)N_NODES * F1];   // x @ W1 (fp16)
__device__ __align__(16) __half g_h2h[(size_t)N_NODES * F1];   // layer-1 out post-ELU (fp16)
__device__ __align__(16) float g_as1[N_NODES * HEADS];
__device__ __align__(16) float g_ad1[N_NODES * HEADS];
__device__ __align__(16) float g_t2[N_NODES * OUT_CH];         // h2 @ W2
__device__ __align__(16) float g_as2[N_NODES];
__device__ __align__(16) float g_ad2[N_NODES];
__device__ __align__(16) __nv_bfloat16 g_xa[(size_t)N_NODES * KP];  // [xhi | xhi]
__device__ __align__(16) __nv_bfloat16 g_wb[(size_t)F1 * KP];       // per-out-col rows [Whi | Wlo]
__device__ int      g_deg[N_NODES + 1];
__device__ int      g_off[N_NODES + 1];
__device__ int      g_cur[N_NODES];
__device__ int      g_esrc[ET];                  // src id per dst-sorted edge
__device__ int      g_is64;
__device__ unsigned g_gmax1[HEADS];              // order-uint global max of as1 per head
__device__ unsigned g_gmax2;                     // order-uint global max of as2
#define NSCB 196                                 // ceil(50000/256)
__device__ int   g_bsum[NSCB];
__device__ int   g_bbase[NSCB];

// ---------------- helpers ----------------
__device__ __forceinline__ uint32_t smem_u32(const void* p) {
    uint32_t a;
    asm("{ .reg .u64 t; cvta.to.shared.u64 t, %1; cvt.u32.u64 %0, t; }" : "=r"(a) : "l"(p));
    return a;
}
template <int N>
__device__ __forceinline__ void cpasync_wait() {
    asm volatile("cp.async.wait_group %0;" :: "n"(N) : "memory");
}
__device__ __forceinline__ void cpasync_commit() {
    asm volatile("cp.async.commit_group;" ::: "memory");
}
__device__ __forceinline__ void cpasync16(uint32_t daddr, const void* gaddr) {
    asm volatile("cp.async.cg.shared.global [%0], [%1], 16;" :: "r"(daddr), "l"(gaddr) : "memory");
}
__device__ __forceinline__ void ldsm_x4(uint32_t& r0, uint32_t& r1, uint32_t& r2, uint32_t& r3,
                                        uint32_t addr) {
    asm volatile("ldmatrix.sync.aligned.m8n8.x4.shared.b16 {%0,%1,%2,%3}, [%4];"
                 : "=r"(r0), "=r"(r1), "=r"(r2), "=r"(r3) : "r"(addr));
}
__device__ __forceinline__ void mma16816(float* d, const uint32_t* a, const uint32_t* b) {
    asm volatile(
        "mma.sync.aligned.m16n8k16.row.col.f32.bf16.bf16.f32 "
        "{%0,%1,%2,%3}, {%4,%5,%6,%7}, {%8,%9}, {%0,%1,%2,%3};"
        : "+f"(d[0]), "+f"(d[1]), "+f"(d[2]), "+f"(d[3])
        : "r"(a[0]), "r"(a[1]), "r"(a[2]), "r"(a[3]), "r"(b[0]), "r"(b[1]));
}
// order-preserving float<->uint for atomicMax on floats
__device__ __forceinline__ unsigned f2o(float f) {
    unsigned u = __float_as_uint(f);
    return u ^ ((u >> 31) ? 0xFFFFFFFFu : 0x80000000u);
}
__device__ __forceinline__ float o2f(unsigned u) {
    u = (u >> 31) ? (u ^ 0x80000000u) : ~u;
    return __uint_as_float(u);
}
__device__ __forceinline__ float lrelu(float x) { return x > 0.f ? x : 0.2f * x; }

// ---------------- bf16 split converts (x and W fused) ----------------
__global__ void k_cvt(const float* __restrict__ x, const float* __restrict__ W) {
    int i = blockIdx.x * blockDim.x + threadIdx.x;
    if (i < N_NODES * IN_CH) {
        int n = i / IN_CH, k = i % IN_CH;
        __nv_bfloat16 hi = __float2bfloat16(x[i]);
        size_t base = (size_t)n * KP;
        g_xa[base + k] = hi;
        g_xa[base + 256 + k] = hi;
    }
    if (i < IN_CH * F1) {
        int k = i / F1, n = i % F1;
        float v = W[i];
        __nv_bfloat16 hi = __float2bfloat16(v);
        __nv_bfloat16 lo = __float2bfloat16(v - __bfloat162float(hi));
        size_t base = (size_t)n * KP;
        g_wb[base + k] = hi;
        g_wb[base + 256 + k] = lo;
    }
}

// ---------------- init: deg, gmax, dtype detect (warp-parallel) ----------------
__global__ void k_init(const int* __restrict__ ei32) {
    int i = blockIdx.x * blockDim.x + threadIdx.x;
    if (i <= N_NODES) g_deg[i] = (i < N_NODES) ? 1 : 0;   // 1 = self loop
    if (i < HEADS) g_gmax1[i] = 0u;
    if (i == HEADS) g_gmax2 = 0u;
    if (blockIdx.x == 0 && threadIdx.x < 32) {
        int v = ei32[2 * threadIdx.x + 1] | ei32[2 * (threadIdx.x + 32) + 1];
        unsigned b = __ballot_sync(0xffffffffu, v != 0);
        if (threadIdx.x == 0) g_is64 = (b == 0) ? 1 : 0;
    }
}
__device__ __forceinline__ int load_idx(const void* __restrict__ ei, int pos) {
    int v;
    if (g_is64) v = (int)((const long long*)ei)[pos];
    else        v = ((const int*)ei)[pos];
    return v < 0 ? 0 : (v >= N_NODES ? N_NODES - 1 : v);
}

// ---------------- CSR build ----------------
__global__ void k_hist(const void* __restrict__ ei) {
    int i = blockIdx.x * blockDim.x + threadIdx.x;
    if (i < N_EDGES) atomicAdd(&g_deg[load_idx(ei, N_EDGES + i)], 1);
}
__global__ void k_scanA() {
    __shared__ int ss[256];
    int t = threadIdx.x, i = blockIdx.x * 256 + t;
    int v = (i < N_NODES) ? g_deg[i] : 0;
    ss[t] = v; __syncthreads();
    for (int o = 1; o < 256; o <<= 1) {
        int u = (t >= o) ? ss[t - o] : 0; __syncthreads();
        ss[t] += u; __syncthreads();
    }
    if (t == 255) g_bsum[blockIdx.x] = ss[255];
}
__global__ void k_scanB() {
    __shared__ int ss[256];
    int t = threadIdx.x;
    int v = (t < NSCB) ? g_bsum[t] : 0;
    ss[t] = v; __syncthreads();
    for (int o = 1; o < 256; o <<= 1) {
        int u = (t >= o) ? ss[t - o] : 0; __syncthreads();
        ss[t] += u; __syncthreads();
    }
    if (t < NSCB) g_bbase[t] = ss[t] - v;
    if (t == 255) g_off[N_NODES] = ss[255];
}
__global__ void k_scanC() {
    __shared__ int ss[256];
    int t = threadIdx.x, i = blockIdx.x * 256 + t;
    int v = (i < N_NODES) ? g_deg[i] : 0;
    ss[t] = v; __syncthreads();
    for (int o = 1; o < 256; o <<= 1) {
        int u = (t >= o) ? ss[t - o] : 0; __syncthreads();
        ss[t] += u; __syncthreads();
    }
    if (i < N_NODES) {
        int off = g_bbase[blockIdx.x] + ss[t] - v;
        g_off[i] = off;
        g_cur[i] = off;
    }
}
__global__ void k_scatter(const void* __restrict__ ei) {
    int i = blockIdx.x * blockDim.x + threadIdx.x;
    if (i >= ET) return;
    int s, d;
    if (i < N_EDGES) { s = load_idx(ei, i); d = load_idx(ei, N_EDGES + i); }
    else             { s = d = i - N_EDGES; }
    int slot = atomicAdd(&g_cur[d], 1);
    if (slot < ET) g_esrc[slot] = s;
}

// ---------------- GEMM1 via mma.sync bf16 (K'=512) + fused logits + gmax ----------------
// CTA 128x128, 8 warps (4m x 2n), warp tile 32x64. 8 K-chunks of 64 bf16.
#define CHUNKS 8

__device__ __forceinline__ void copy_chunk(uint32_t sA, uint32_t sB, int bm, int bn,
                                           int k0, int tid) {
#pragma unroll
    for (int it = 0; it < 4; it++) {
        int flat = it * 256 + tid;      // 0..1023 16B units
        int r = flat >> 3, q = flat & 7;
        int m = bm + r; if (m >= N_NODES) m = N_NODES - 1;
        uint32_t sw = (uint32_t)(r * 8 + (q ^ (r & 7))) * 16;
        cpasync16(sA + sw, (const char*)g_xa + ((size_t)m * KP + k0 + q * 8) * 2);
        cpasync16(sB + sw, (const char*)g_wb + ((size_t)(bn * 128 + r) * KP + k0 + q * 8) * 2);
    }
    cpasync_commit();
}

__global__ __launch_bounds__(256) void k_gemm1_mma(const float* __restrict__ att_s,
                                                   const float* __restrict__ att_d) {
    extern __shared__ __align__(1024) char smem[];
    __shared__ float satt[256];
    const uint32_t sb = smem_u32(smem);
    const int tid = threadIdx.x, wid = tid >> 5, lane = tid & 31;
    const int warp_m = wid & 3, warp_n = wid >> 2;
    const int bm = blockIdx.x * 128;
    const int bn = blockIdx.y;

    for (int i = tid; i < 128; i += 256) {
        satt[i]       = att_s[bn * 128 + i];
        satt[128 + i] = att_d[bn * 128 + i];
    }

    float d[2][8][4];
#pragma unroll
    for (int g = 0; g < 2; g++)
#pragma unroll
        for (int nf = 0; nf < 8; nf++)
#pragma unroll
            for (int q = 0; q < 4; q++) d[g][nf][q] = 0.f;

    copy_chunk(sb, sb + 16384, bm, bn, 0, tid);

    for (int ch = 0; ch < CHUNKS; ch++) {
        uint32_t curA = sb + (ch & 1) * 32768;
        uint32_t curB = curA + 16384;
        if (ch + 1 < CHUNKS) {
            copy_chunk(sb + ((ch + 1) & 1) * 32768, sb + ((ch + 1) & 1) * 32768 + 16384,
                       bm, bn, (ch + 1) * 64, tid);
            cpasync_wait<1>();
        } else {
            cpasync_wait<0>();
        }
        __syncthreads();

#pragma unroll
        for (int ks = 0; ks < 4; ks++) {
            uint32_t a[2][4];
#pragma unroll
            for (int g = 0; g < 2; g++) {
                int rA = warp_m * 32 + g * 16 + (lane & 15);
                int u = ks * 2 + (lane >> 4);
                ldsm_x4(a[g][0], a[g][1], a[g][2], a[g][3],
                        curA + (uint32_t)(rA * 8 + (u ^ (rA & 7))) * 16);
            }
            uint32_t b[8][2];
#pragma unroll
            for (int nf2 = 0; nf2 < 4; nf2++) {
                int rB = warp_n * 64 + nf2 * 16 + (lane & 7) + ((lane >> 4) & 1) * 8;
                int u = ks * 2 + ((lane >> 3) & 1);
                ldsm_x4(b[nf2 * 2][0], b[nf2 * 2][1], b[nf2 * 2 + 1][0], b[nf2 * 2 + 1][1],
                        curB + (uint32_t)(rB * 8 + (u ^ (rB & 7))) * 16);
            }
#pragma unroll
            for (int g = 0; g < 2; g++)
#pragma unroll
                for (int nf = 0; nf < 8; nf++)
                    mma16816(d[g][nf], a[g], b[nf]);
        }
        __syncthreads();
    }

    // epilogue: fused logits (head = bn*2 + warp_n) + h1 (fp16) stores + global a_src max
    const int head = bn * 2 + warp_n;
    float mx = -1e30f;
#pragma unroll
    for (int g = 0; g < 2; g++) {
        float sl0 = 0.f, sl1 = 0.f, dl0 = 0.f, dl1 = 0.f;
        int r0 = bm + warp_m * 32 + g * 16 + (lane >> 2);
        bool ok0 = r0 < N_NODES, ok1 = (r0 + 8) < N_NODES;
#pragma unroll
        for (int nf = 0; nf < 8; nf++) {
            int j = warp_n * 64 + nf * 8 + 2 * (lane & 3);
            float a0 = satt[j], a1 = satt[j + 1];
            float c0 = satt[128 + j], c1 = satt[128 + j + 1];
            float v0 = d[g][nf][0], v1 = d[g][nf][1];
            float v2 = d[g][nf][2], v3 = d[g][nf][3];
            sl0 += v0 * a0 + v1 * a1;  dl0 += v0 * c0 + v1 * c1;
            sl1 += v2 * a0 + v3 * a1;  dl1 += v2 * c0 + v3 * c1;
            size_t cb = (size_t)bn * 128 + j;
            if (ok0) *(__half2*)&g_h1h[(size_t)r0 * F1 + cb] = __floats2half2_rn(v0, v1);
            if (ok1) *(__half2*)&g_h1h[(size_t)(r0 + 8) * F1 + cb] = __floats2half2_rn(v2, v3);
        }
        sl0 += __shfl_xor_sync(0xffffffffu, sl0, 1); sl0 += __shfl_xor_sync(0xffffffffu, sl0, 2);
        sl1 += __shfl_xor_sync(0xffffffffu, sl1, 1); sl1 += __shfl_xor_sync(0xffffffffu, sl1, 2);
        dl0 += __shfl_xor_sync(0xffffffffu, dl0, 1); dl0 += __shfl_xor_sync(0xffffffffu, dl0, 2);
        dl1 += __shfl_xor_sync(0xffffffffu, dl1, 1); dl1 += __shfl_xor_sync(0xffffffffu, dl1, 2);
        if (ok0) mx = fmaxf(mx, sl0);
        if (ok1) mx = fmaxf(mx, sl1);
        if ((lane & 3) == 0) {
            if (ok0) { g_as1[r0 * HEADS + head] = sl0; g_ad1[r0 * HEADS + head] = dl0; }
            if (ok1) { g_as1[(r0 + 8) * HEADS + head] = sl1; g_ad1[(r0 + 8) * HEADS + head] = dl1; }
        }
    }
#pragma unroll
    for (int off = 16; off >= 1; off >>= 1)
        mx = fmaxf(mx, __shfl_xor_sync(0xffffffffu, mx, off));
    if (lane == 0) atomicMax(&g_gmax1[head], f2o(mx));
}

// ---------------- layer-1 aggregation (fp16 gather, no max pass, pipelined) ----------------
__global__ void k_agg1(const float* __restrict__ b1) {
    int n = (blockIdx.x * blockDim.x + threadIdx.x) >> 5;
    int lane = threadIdx.x & 31;
    if (n >= N_NODES) return;
    const int o0 = g_off[n], o1 = g_off[n + 1];
    const int head = lane >> 2;
    const float myadn = g_ad1[n * HEADS + head];
    const float m = lrelu(o2f(g_gmax1[head]) + myadn);   // upper bound of all edge logits

    float denom = 0.f;
    float acc[16];
#pragma unroll
    for (int q = 0; q < 16; q++) acc[q] = 0.f;

    // pipelined: src index 2 ahead, logits + data 1 ahead. lane owns halves [lane*16, lane*16+16)
    int s1 = g_esrc[o0];
    int s2 = (o0 + 1 < o1) ? g_esrc[o0 + 1] : s1;
    float a_cur = g_as1[(size_t)s1 * HEADS + head];
    const uint4* p = (const uint4*)(g_h1h + (size_t)s1 * F1) + lane * 2;
    uint4 t0 = p[0], t1 = p[1];
    s1 = s2;

    for (int e = o0; e < o1; e++) {
        int s3 = (e + 2 < o1) ? g_esrc[e + 2] : s1;
        float a_nxt = 0.f;
        uint4 u0, u1;
        if (e + 1 < o1) {
            a_nxt = g_as1[(size_t)s1 * HEADS + head];
            const uint4* q = (const uint4*)(g_h1h + (size_t)s1 * F1) + lane * 2;
            u0 = q[0]; u1 = q[1];
        } else {
            u0 = make_uint4(0, 0, 0, 0); u1 = u0;
        }
        float w = __expf(lrelu(a_cur + myadn) - m);
        denom += w;
        const __half2* hp = (const __half2*)&t0;
#pragma unroll
        for (int q2 = 0; q2 < 4; q2++) {
            float2 f = __half22float2(hp[q2]);
            acc[2 * q2]     = fmaf(w, f.x, acc[2 * q2]);
            acc[2 * q2 + 1] = fmaf(w, f.y, acc[2 * q2 + 1]);
        }
        const __half2* hq = (const __half2*)&t1;
#pragma unroll
        for (int q2 = 0; q2 < 4; q2++) {
            float2 f = __half22float2(hq[q2]);
            acc[8 + 2 * q2]     = fmaf(w, f.x, acc[8 + 2 * q2]);
            acc[8 + 2 * q2 + 1] = fmaf(w, f.y, acc[8 + 2 * q2 + 1]);
        }
        s1 = s3; a_cur = a_nxt;
        t0 = u0; t1 = u1;
    }
    const float inv = 1.0f / (denom + 1e-16f);
    // bias + ELU, store h2 as fp16 (lane owns cols [lane*16, lane*16+16))
    __half2 hout[8];
#pragma unroll
    for (int q = 0; q < 4; q++) {
        float4 bq = ((const float4*)b1)[lane * 4 + q];
        float x0 = acc[q * 4 + 0] * inv + bq.x;
        float x1 = acc[q * 4 + 1] * inv + bq.y;
        float x2 = acc[q * 4 + 2] * inv + bq.z;
        float x3 = acc[q * 4 + 3] * inv + bq.w;
        x0 = x0 > 0.f ? x0 : (__expf(x0) - 1.f);
        x1 = x1 > 0.f ? x1 : (__expf(x1) - 1.f);
        x2 = x2 > 0.f ? x2 : (__expf(x2) - 1.f);
        x3 = x3 > 0.f ? x3 : (__expf(x3) - 1.f);
        hout[q * 2]     = __floats2half2_rn(x0, x1);
        hout[q * 2 + 1] = __floats2half2_rn(x2, x3);
    }
    uint4* outp = (uint4*)(g_h2h + (size_t)n * F1) + lane * 2;
    outp[0] = *(uint4*)&hout[0];
    outp[1] = *(uint4*)&hout[4];
}

// ---------------- GEMM2 (h2 fp16 @ W2, 512->16) + layer-2 logits + gmax ----------------
__global__ __launch_bounds__(256) void k_gemm2(const float* __restrict__ W2,
                                               const float* __restrict__ att_s2,
                                               const float* __restrict__ att_d2) {
    __shared__ __align__(16) float sW[F1 * OUT_CH];
    __shared__ float sAs[OUT_CH], sAd[OUT_CH];
    int tid = threadIdx.x;
    for (int i = tid; i < F1 * OUT_CH / 4; i += 256)
        ((float4*)sW)[i] = ((const float4*)W2)[i];
    if (tid < OUT_CH) { sAs[tid] = att_s2[tid]; sAd[tid] = att_d2[tid]; }
    __syncthreads();
    int n = blockIdx.x * 16 + tid / 16;
    int c = tid % 16;
    if (n >= N_NODES) return;
    const __half2* row = (const __half2*)(g_h2h + (size_t)n * F1);
    float acc = 0.f;
#pragma unroll 16
    for (int k2 = 0; k2 < F1 / 2; k2++) {
        float2 f = __half22float2(row[k2]);
        acc = fmaf(f.x, sW[(2 * k2) * OUT_CH + c], acc);
        acc = fmaf(f.y, sW[(2 * k2 + 1) * OUT_CH + c], acc);
    }
    g_t2[n * OUT_CH + c] = acc;
    float ls = acc * sAs[c];
    float ld_ = acc * sAd[c];
#pragma unroll
    for (int off = 8; off >= 1; off >>= 1) {
        ls  += __shfl_xor_sync(0xffffffffu, ls, off);
        ld_ += __shfl_xor_sync(0xffffffffu, ld_, off);
    }
    if (c == 0) { g_as2[n] = ls; g_ad2[n] = ld_; }
    float mx = fmaxf(ls, __shfl_xor_sync(0xffffffffu, ls, 16));
    if ((tid & 31) == 0) atomicMax(&g_gmax2, f2o(mx));
}

// ---------------- layer-2 aggregation (no max pass; pipelined) + log_softmax ----------------
__global__ void k_agg2(const float* __restrict__ b2, float* __restrict__ out) {
    int n = (blockIdx.x * blockDim.x + threadIdx.x) >> 5;
    int lane = threadIdx.x & 31;
    if (n >= N_NODES) return;
    const int o0 = g_off[n], o1 = g_off[n + 1];
    const float adn = g_ad2[n];
    const float m = lrelu(o2f(g_gmax2) + adn);

    float denom = 0.f, acc = 0.f;
    int c = lane & 15;

    int s1 = g_esrc[o0];
    int s2 = (o0 + 1 < o1) ? g_esrc[o0 + 1] : s1;
    float a_cur = g_as2[s1];
    float t_cur = g_t2[(size_t)s1 * OUT_CH + c];
    s1 = s2;

    for (int e = o0; e < o1; e++) {
        int s3 = (e + 2 < o1) ? g_esrc[e + 2] : s1;
        float a_nxt = 0.f, t_nxt = 0.f;
        if (e + 1 < o1) {
            a_nxt = g_as2[s1];
            t_nxt = g_t2[(size_t)s1 * OUT_CH + c];
        }
        float w = __expf(lrelu(a_cur + adn) - m);
        denom += w;
        acc = fmaf(w, t_cur, acc);
        s1 = s3; a_cur = a_nxt; t_cur = t_nxt;
    }
    float o = acc / (denom + 1e-16f) + b2[c];
    float mx = o;
#pragma unroll
    for (int off = 8; off >= 1; off >>= 1)
        mx = fmaxf(mx, __shfl_xor_sync(0xffffffffu, mx, off));
    float ex = __expf(o - mx);
    float sm = ex;
#pragma unroll
    for (int off = 8; off >= 1; off >>= 1)
        sm += __shfl_xor_sync(0xffffffffu, sm, off);
    float res = o - mx - logf(sm);
    if (lane < 16) out[(size_t)n * OUT_CH + lane] = res;
}

// ---------------- launch ----------------
extern "C" void kernel_launch(void* const* d_in, const int* in_sizes, int n_in,
                              void* d_out, int out_size) {
    const float* x    = (const float*)d_in[0];
    const void*  ei   = d_in[1];
    const float* W1   = (const float*)d_in[2];
    const float* as1  = (const float*)d_in[3];
    const float* ad1  = (const float*)d_in[4];
    const float* b1   = (const float*)d_in[5];
    const float* W2   = (const float*)d_in[6];
    const float* as2  = (const float*)d_in[7];
    const float* ad2  = (const float*)d_in[8];
    const float* b2   = (const float*)d_in[9];
    float* out = (float*)d_out;

    cudaFuncSetAttribute(k_gemm1_mma, cudaFuncAttributeMaxDynamicSharedMemorySize, 65536);

    k_cvt<<<(N_NODES * IN_CH + 255) / 256, 256>>>(x, W1);
    k_init<<<(N_NODES + 256) / 256, 256>>>((const int*)ei);
    k_hist<<<(N_EDGES + 255) / 256, 256>>>(ei);

    dim3 g1((N_NODES + 127) / 128, 4);
    k_gemm1_mma<<<g1, 256, 65536>>>(as1, ad1);

    k_scanA<<<NSCB, 256>>>();
    k_scanB<<<1, 256>>>();
    k_scanC<<<NSCB, 256>>>();
    k_scatter<<<(ET + 255) / 256, 256>>>(ei);

    k_agg1<<<(N_NODES + 7) / 8, 256>>>(b1);

    k_gemm2<<<N_NODES / 16, 256>>>(W2, as2, ad2);
    k_agg2<<<(N_NODES + 7) / 8, 256>>>(b2, out);
}